// round 12
// baseline (speedup 1.0000x reference)
#include <cuda_runtime.h>
#include <cstdint>
#include <cuda_fp16.h>
#include <mma.h>
#include <math.h>

using namespace nvcuda;

#define HH 512
#define SS 6
#define MAXB 16384
#define KC 576      // comb K: 512 attn_applied + input + bias + pad to 64 ; also gates-final K
#define KH 512      // Hpart K: hidden

// ---- scratch (static device globals; no runtime allocation) ----
__device__ __align__(16) __half g_Xc   [(size_t)MAXB * KC];
__device__ __align__(16) __half g_Abig [(size_t)MAXB * KC];   // [relu(comb) | 1 | 0pad]
__device__ __align__(16) __half g_Hh   [(size_t)MAXB * KH];   // fp16 copy of hidden
__device__ __align__(16) float  g_Hp   [(size_t)MAXB * 4 * HH]; // hidden @ W_hh^T, interleaved n'=4j+g
__device__ __align__(16) __half g_Wc   [HH * KC];
__device__ __align__(16) __half g_Wg   [4 * HH * KC];         // [W_ih | b_ih+b_hh | 0], rows n'=4j+g
__device__ __align__(16) __half g_Whh  [4 * HH * KH];         // W_hh, rows n'=4j+g

__device__ __forceinline__ float sigm_fast(float x) {
    return __fdividef(1.f, 1.f + __expf(-x));
}
__device__ __forceinline__ float tanh_fast(float x) {
    return __fmaf_rn(2.f, sigm_fast(2.f * x), -1.f);
}

// ---- build padded weight matrices (fp16); g_Wg/g_Whh rows n' = 4*j + g, torch row g*512+j ----
__global__ void init_weights(const float* __restrict__ Wcomb, const float* __restrict__ bcomb,
                             const float* __restrict__ Wih,   const float* __restrict__ Whh,
                             const float* __restrict__ bih,   const float* __restrict__ bhh) {
    int idx = blockIdx.x * blockDim.x + threadIdx.x;
    int stride = gridDim.x * blockDim.x;
    for (int i = idx; i < HH * KC; i += stride) {
        int n = i / KC, k = i % KC;
        float v = 0.f;
        if (k < 512)        v = Wcomb[n * 513 + 1 + k];
        else if (k == 512)  v = Wcomb[n * 513];
        else if (k == 513)  v = bcomb[n];
        g_Wc[i] = __float2half_rn(v);
    }
    for (int i = idx; i < 4 * HH * KC; i += stride) {
        int np = i / KC, k = i % KC;
        int j = np >> 2, g = np & 3;
        int n = g * 512 + j;
        float v = 0.f;
        if (k < 512)        v = Wih[n * 512 + k];
        else if (k == 512)  v = bih[n] + bhh[n];
        g_Wg[i] = __float2half_rn(v);
    }
    for (int i = idx; i < 4 * HH * KH; i += stride) {
        int np = i / KH, k = i % KH;
        int j = np >> 2, g = np & 3;
        int n = g * 512 + j;
        g_Whh[i] = __float2half_rn(Whh[n * 512 + k]);
    }
}

// ---- hidden f32 -> fp16 ----
__global__ void convert_hidden(const float* __restrict__ hidden) {
    int i = blockIdx.x * blockDim.x + threadIdx.x;       // half2 index
    int n2 = MAXB * KH / 2;
    if (i < n2) {
        float2 f = ((const float2*)hidden)[i];
        ((__half2*)g_Hh)[i] = __floats2half2_rn(f.x, f.y);
    }
}

// ---- attention: logits -> softmax -> weighted sum; builds fp16 Xc + Abig tail ----
__global__ void attn_kernel(const float* __restrict__ input, const float* __restrict__ hidden,
                            const float* __restrict__ cell,  const float* __restrict__ enc,
                            const float* __restrict__ Wattn, const float* __restrict__ battn,
                            float* __restrict__ out_attnw) {
    int b = blockIdx.x;
    int tid = threadIdx.x;             // 256 threads
    __shared__ float s_w[SS];
    __shared__ float s_part[8][SS];

    float h0 = hidden[(size_t)b * HH + tid];
    float h1 = hidden[(size_t)b * HH + tid + 256];
    float c0 = cell  [(size_t)b * HH + tid];
    float c1 = cell  [(size_t)b * HH + tid + 256];

    float p[SS];
#pragma unroll
    for (int s = 0; s < SS; s++) {
        const float* wr = Wattn + s * 1025;
        p[s] = wr[1 + tid] * h0 + wr[1 + tid + 256] * h1
             + wr[513 + tid] * c0 + wr[513 + tid + 256] * c1;
    }
#pragma unroll
    for (int s = 0; s < SS; s++)
#pragma unroll
        for (int off = 16; off; off >>= 1)
            p[s] += __shfl_down_sync(0xffffffffu, p[s], off);
    int warp = tid >> 5, lane = tid & 31;
    if (lane == 0)
#pragma unroll
        for (int s = 0; s < SS; s++) s_part[warp][s] = p[s];
    __syncthreads();

    if (tid == 0) {
        float inp = input[b];
        float lg[SS], mx = -1e30f;
#pragma unroll
        for (int s = 0; s < SS; s++) {
            float v = battn[s] + Wattn[s * 1025] * inp;
#pragma unroll
            for (int w = 0; w < 8; w++) v += s_part[w][s];
            lg[s] = v; mx = fmaxf(mx, v);
        }
        float sum = 0.f;
#pragma unroll
        for (int s = 0; s < SS; s++) { lg[s] = expf(lg[s] - mx); sum += lg[s]; }
        float inv = 1.f / sum;
#pragma unroll
        for (int s = 0; s < SS; s++) {
            float w = lg[s] * inv;
            s_w[s] = w;
            out_attnw[(size_t)b * SS + s] = w;
        }
    }
    __syncthreads();

    float w0 = s_w[0], w1 = s_w[1], w2 = s_w[2], w3 = s_w[3], w4 = s_w[4], w5 = s_w[5];
    const float* eb = enc + (size_t)b * SS * HH;
#pragma unroll
    for (int r = 0; r < 2; r++) {
        int k = tid + r * 256;
        float a = w0 * eb[k]          + w1 * eb[HH + k]     + w2 * eb[2 * HH + k]
                + w3 * eb[3 * HH + k] + w4 * eb[4 * HH + k] + w5 * eb[5 * HH + k];
        g_Xc[(size_t)b * KC + k] = __float2half_rn(a);
    }
    if (tid < 64) {
        float v = 0.f;
        if (tid == 0) v = input[b];
        else if (tid == 1) v = 1.f;
        g_Xc[(size_t)b * KC + 512 + tid] = __float2half_rn(v);
        float u = (tid == 0) ? 1.f : 0.f;
        g_Abig[(size_t)b * KC + 512 + tid] = __float2half_rn(u);
    }
}

// ---- fp16 wmma GEMM, 128x128 tile, 4 warps (64x64/warp), BK=64, 2-stage cp.async ----
// EPI 0: relu -> half C (comb)    EPI 1: LSTM + Hp add (gates)    EPI 2: plain f32 store (Hpart)
#define CP16(dst_u32, src_ptr) \
    asm volatile("cp.async.cg.shared.global [%0], [%1], 16;" :: "r"(dst_u32), "l"(src_ptr))

template <int EPI>
__global__ void __launch_bounds__(128, 3)
gemm_fp16(const __half* __restrict__ A, int lda,
          const __half* __restrict__ Bw, int ldb,
          void* __restrict__ Cv, int ldc, int K,
          const float* __restrict__ cell, const float* __restrict__ hp,
          float* __restrict__ o_h, float* __restrict__ o_c) {
    constexpr int BM = 128, BN = 128, BK = 64, PAD = 72;
    extern __shared__ __half smem[];
    __half* As = smem;
    __half* Bs = smem + 2 * BM * PAD;

    int m0 = blockIdx.y * BM, n0 = blockIdx.x * BN;
    int tid = threadIdx.x;
    int warp = tid >> 5, lane = tid & 31;
    int wr = warp & 1;
    int wc = warp >> 1;

    wmma::fragment<wmma::accumulator, 16, 16, 16, float> acc[4][4];
#pragma unroll
    for (int i = 0; i < 4; i++)
#pragma unroll
        for (int j = 0; j < 4; j++) wmma::fill_fragment(acc[i][j], 0.f);

    int nk = K / BK;

    auto stage_copy = [&](int st, int k0) {
#pragma unroll
        for (int i = 0; i < 8; i++) {
            int q = tid + i * 128;
            int row = q >> 3, c8 = (q & 7) << 3;
            const __half* ga = &A[(size_t)(m0 + row) * lda + k0 + c8];
            unsigned int sa = (unsigned int)__cvta_generic_to_shared(&As[st * BM * PAD + row * PAD + c8]);
            CP16(sa, ga);
            const __half* gb = &Bw[(size_t)(n0 + row) * ldb + k0 + c8];
            unsigned int sb = (unsigned int)__cvta_generic_to_shared(&Bs[st * BN * PAD + row * PAD + c8]);
            CP16(sb, gb);
        }
        asm volatile("cp.async.commit_group;");
    };

    stage_copy(0, 0);

    for (int t = 0; t < nk; t++) {
        asm volatile("cp.async.wait_group 0;");
        __syncthreads();
        if (t + 1 < nk) stage_copy((t + 1) & 1, (t + 1) * BK);

        const __half* Ab = &As[(t & 1) * BM * PAD];
        const __half* Bb = &Bs[(t & 1) * BN * PAD];
#pragma unroll
        for (int kk = 0; kk < 4; kk++) {
            wmma::fragment<wmma::matrix_a, 16, 16, 16, __half, wmma::row_major> af[4];
            wmma::fragment<wmma::matrix_b, 16, 16, 16, __half, wmma::col_major> bf[4];
#pragma unroll
            for (int i = 0; i < 4; i++)
                wmma::load_matrix_sync(af[i], &Ab[(wr * 64 + i * 16) * PAD + kk * 16], PAD);
#pragma unroll
            for (int j = 0; j < 4; j++)
                wmma::load_matrix_sync(bf[j], &Bb[(wc * 64 + j * 16) * PAD + kk * 16], PAD);
#pragma unroll
            for (int i = 0; i < 4; i++)
#pragma unroll
                for (int j = 0; j < 4; j++)
                    wmma::mma_sync(acc[i][j], af[i], bf[j], acc[i][j]);
        }
    }

    if (EPI == 2) {
        // plain f32 store (Hpart partial)
        float* Cf = (float*)Cv;
#pragma unroll
        for (int i = 0; i < 4; i++)
#pragma unroll
            for (int j = 0; j < 4; j++)
                wmma::store_matrix_sync(
                    &Cf[(size_t)(m0 + wr * 64 + i * 16) * ldc + n0 + wc * 64 + j * 16],
                    acc[i][j], ldc, wmma::mem_row_major);
        return;
    }

    // ---- staged epilogues ----
    __syncthreads();
    float* stg = (float*)smem;
    constexpr int LDS_ = 68;
    float* wbase = stg + warp * 64 * LDS_;
#pragma unroll
    for (int i = 0; i < 4; i++)
#pragma unroll
        for (int j = 0; j < 4; j++)
            wmma::store_matrix_sync(&wbase[(i * 16) * LDS_ + j * 16], acc[i][j],
                                    LDS_, wmma::mem_row_major);
    __syncwarp();

    if (EPI == 0) {
        __half* Ch = (__half*)Cv;
        for (int r = lane; r < 64; r += 32) {
            size_t grow = (size_t)(m0 + wr * 64 + r) * ldc + n0 + wc * 64;
#pragma unroll
            for (int c = 0; c < 64; c += 2) {
                float x = fmaxf(wbase[r * LDS_ + c], 0.f);
                float y = fmaxf(wbase[r * LDS_ + c + 1], 0.f);
                *(__half2*)&Ch[grow + c] = __floats2half2_rn(x, y);
            }
        }
    } else {
        int nbase = n0 + wc * 64;            // column base in interleaved n' units
        int jbase = nbase >> 2;
#pragma unroll 4
        for (int it = 0; it < 32; it++) {
            int idx = it * 32 + lane;
            int r = idx >> 4, jj = idx & 15;
            int b = m0 + wr * 64 + r;
            int j = jbase + jj;
            const float* cellrow = &wbase[r * LDS_ + jj * 4];
            float4 hv = *(const float4*)&hp[(size_t)b * 2048 + nbase + jj * 4];
            float gi = cellrow[0] + hv.x;
            float gf = cellrow[1] + hv.y;
            float gg = cellrow[2] + hv.z;
            float go = cellrow[3] + hv.w;
            float c_old = cell[(size_t)b * HH + j];
            float si = sigm_fast(gi);
            float sf = sigm_fast(gf);
            float so = sigm_fast(go);
            float tg = tanh_fast(gg);
            float cn = sf * c_old + si * tg;
            float hn = so * tanh_fast(cn);
            o_c[(size_t)b * HH + j] = cn;
            o_h[(size_t)b * HH + j] = hn;
        }
    }
}

// ---- output dot: out[b] = dot(o_h[b,:], Wout) + bout ----
__global__ void dot_kernel(const float* __restrict__ o_h, const float* __restrict__ Wout,
                           const float* __restrict__ bout, float* __restrict__ out_output) {
    int b = blockIdx.x, j = threadIdx.x;   // 512 threads
    float part = o_h[(size_t)b * HH + j] * Wout[j];
#pragma unroll
    for (int off = 16; off; off >>= 1) part += __shfl_down_sync(0xffffffffu, part, off);
    __shared__ float sp[16];
    if ((j & 31) == 0) sp[j >> 5] = part;
    __syncthreads();
    if (j < 16) {
        float v = sp[j];
#pragma unroll
        for (int off = 8; off; off >>= 1) v += __shfl_down_sync(0xffffu, v, off);
        if (j == 0) out_output[b] = v + bout[0];
    }
}

extern "C" void kernel_launch(void* const* d_in, const int* in_sizes, int n_in,
                              void* d_out, int out_size) {
    const float* input  = (const float*)d_in[0];
    const float* hidden = (const float*)d_in[1];
    const float* cell   = (const float*)d_in[2];
    const float* enc    = (const float*)d_in[3];
    const float* Wattn  = (const float*)d_in[4];
    const float* battn  = (const float*)d_in[5];
    const float* Wcomb  = (const float*)d_in[6];
    const float* bcomb  = (const float*)d_in[7];
    const float* Wih    = (const float*)d_in[8];
    const float* Whh    = (const float*)d_in[9];
    const float* bih    = (const float*)d_in[10];
    const float* bhh    = (const float*)d_in[11];
    const float* Wout   = (const float*)d_in[12];
    const float* bout   = (const float*)d_in[13];

    int B = in_sizes[1] / HH;   // 16384

    float* out      = (float*)d_out;
    float* o_output = out;                              // [B, 1]
    float* o_h      = out + (size_t)B;                  // [B, H]
    float* o_c      = o_h + (size_t)B * HH;             // [B, H]
    float* o_aw     = o_c + (size_t)B * HH;             // [B, 1, S]

    __half *pXc, *pAbig, *pHh, *pWc, *pWg, *pWhh;
    float *pHp;
    cudaGetSymbolAddress((void**)&pXc,   g_Xc);
    cudaGetSymbolAddress((void**)&pAbig, g_Abig);
    cudaGetSymbolAddress((void**)&pHh,   g_Hh);
    cudaGetSymbolAddress((void**)&pHp,   g_Hp);
    cudaGetSymbolAddress((void**)&pWc,   g_Wc);
    cudaGetSymbolAddress((void**)&pWg,   g_Wg);
    cudaGetSymbolAddress((void**)&pWhh,  g_Whh);

    constexpr int SMEMB = 2 * 2 * 128 * 72 * (int)sizeof(__half);   // 73728
    cudaFuncSetAttribute((const void*)gemm_fp16<0>,
                         cudaFuncAttributeMaxDynamicSharedMemorySize, SMEMB);
    cudaFuncSetAttribute((const void*)gemm_fp16<1>,
                         cudaFuncAttributeMaxDynamicSharedMemorySize, SMEMB);
    cudaFuncSetAttribute((const void*)gemm_fp16<2>,
                         cudaFuncAttributeMaxDynamicSharedMemorySize, SMEMB);

    // one-time stream/event creation (host resources; no device allocation)
    static cudaStream_t s2 = nullptr;
    static cudaEvent_t evA = nullptr, evB = nullptr;
    if (!s2) {
        cudaStreamCreateWithFlags(&s2, cudaStreamNonBlocking);
        cudaEventCreateWithFlags(&evA, cudaEventDisableTiming);
        cudaEventCreateWithFlags(&evB, cudaEventDisableTiming);
    }

    // main: weight prep + hidden convert
    init_weights<<<512, 256>>>(Wcomb, bcomb, Wih, Whh, bih, bhh);
    convert_hidden<<<(MAXB * KH / 2 + 255) / 256, 256>>>(hidden);

    // fork: Hpart = g_Hh @ g_Whh^T on s2, concurrent with attn + comb on main
    cudaEventRecord(evA, 0);
    cudaStreamWaitEvent(s2, evA, 0);
    {
        dim3 grid((4 * HH) / 128, B / 128);
        gemm_fp16<2><<<grid, 128, SMEMB, s2>>>(pHh, KH, pWhh, KH, pHp, 4 * HH, KH,
                                               nullptr, nullptr, nullptr, nullptr);
    }

    attn_kernel<<<B, 256>>>(input, hidden, cell, enc, Wattn, battn, o_aw);
    {
        dim3 grid(HH / 128, B / 128);
        gemm_fp16<0><<<grid, 128, SMEMB>>>(pXc, KC, pWc, KC, pAbig, KC, KC,
                                           nullptr, nullptr, nullptr, nullptr);
    }

    // join: gates-final needs Hpart
    cudaEventRecord(evB, s2);
    cudaStreamWaitEvent(0, evB, 0);
    {
        dim3 grid((4 * HH) / 128, B / 128);
        gemm_fp16<1><<<grid, 128, SMEMB>>>(pAbig, KC, pWg, KC, nullptr, 0, KC,
                                           cell, pHp, o_h, o_c);
    }
    dot_kernel<<<B, 512>>>(o_h, Wout, bout, o_output);
}

// round 13
// speedup vs baseline: 1.1881x; 1.1881x over previous
#include <cuda_runtime.h>
#include <cstdint>
#include <cuda_fp16.h>
#include <mma.h>
#include <math.h>

using namespace nvcuda;

#define HH 512
#define SS 6
#define MAXB 16384
#define KC 576      // comb K: 512 attn_applied + input + bias + pad to 64
#define KG 1088     // gates K: 512 x + 512 hidden + bias + pad to 64

// ---- scratch (static device globals; no runtime allocation) ----
__device__ __align__(16) __half g_Xc  [(size_t)MAXB * KC];
__device__ __align__(16) __half g_Abig[(size_t)MAXB * KG];
__device__ __align__(16) __half g_Wc  [HH * KC];
__device__ __align__(16) __half g_Wg  [4 * HH * KG];   // rows interleaved: n' = 4*j + gate

__device__ __forceinline__ float sigm_fast(float x) {
    return __fdividef(1.f, 1.f + __expf(-x));
}
__device__ __forceinline__ float tanh_fast(float x) {
    return __fmaf_rn(2.f, sigm_fast(2.f * x), -1.f);
}

// ---- build padded weight matrices (fp16) ----
// g_Wg row n' = 4*j + g  maps to torch row  n_old = g*512 + j  (gate order i,f,g,o)
__global__ void init_weights(const float* __restrict__ Wcomb, const float* __restrict__ bcomb,
                             const float* __restrict__ Wih,   const float* __restrict__ Whh,
                             const float* __restrict__ bih,   const float* __restrict__ bhh) {
    int idx = blockIdx.x * blockDim.x + threadIdx.x;
    int stride = gridDim.x * blockDim.x;
    for (int i = idx; i < HH * KC; i += stride) {
        int n = i / KC, k = i % KC;
        float v = 0.f;
        if (k < 512)        v = Wcomb[n * 513 + 1 + k];
        else if (k == 512)  v = Wcomb[n * 513];
        else if (k == 513)  v = bcomb[n];
        g_Wc[i] = __float2half_rn(v);
    }
    for (int i = idx; i < 4 * HH * KG; i += stride) {
        int np = i / KG, k = i % KG;
        int j = np >> 2, g = np & 3;
        int n = g * 512 + j;               // torch gate-major row
        float v = 0.f;
        if (k < 512)        v = Wih[n * 512 + k];
        else if (k < 1024)  v = Whh[n * 512 + (k - 512)];
        else if (k == 1024) v = bih[n] + bhh[n];
        g_Wg[i] = __float2half_rn(v);
    }
}

// ---- attention: 128 threads/block, float4 loads, fp16 operand stores ----
__global__ void attn_kernel(const float* __restrict__ input, const float* __restrict__ hidden,
                            const float* __restrict__ cell,  const float* __restrict__ enc,
                            const float* __restrict__ Wattn, const float* __restrict__ battn,
                            float* __restrict__ out_attnw) {
    int b = blockIdx.x;
    int tid = threadIdx.x;             // 128 threads; each owns 4 consecutive columns
    int k4 = tid << 2;
    __shared__ float s_w[SS];
    __shared__ float s_part[4][SS];

    float4 h4 = *(const float4*)&hidden[(size_t)b * HH + k4];
    float4 c4 = *(const float4*)&cell  [(size_t)b * HH + k4];

    float p[SS];
#pragma unroll
    for (int s = 0; s < SS; s++) {
        const float* wr = Wattn + s * 1025;
        float v;
        v  = wr[1 + k4]     * h4.x;
        v  = __fmaf_rn(wr[2 + k4],   h4.y, v);
        v  = __fmaf_rn(wr[3 + k4],   h4.z, v);
        v  = __fmaf_rn(wr[4 + k4],   h4.w, v);
        v  = __fmaf_rn(wr[513 + k4], c4.x, v);
        v  = __fmaf_rn(wr[514 + k4], c4.y, v);
        v  = __fmaf_rn(wr[515 + k4], c4.z, v);
        v  = __fmaf_rn(wr[516 + k4], c4.w, v);
        p[s] = v;
    }
#pragma unroll
    for (int s = 0; s < SS; s++)
#pragma unroll
        for (int off = 16; off; off >>= 1)
            p[s] += __shfl_down_sync(0xffffffffu, p[s], off);
    int warp = tid >> 5, lane = tid & 31;
    if (lane == 0)
#pragma unroll
        for (int s = 0; s < SS; s++) s_part[warp][s] = p[s];
    __syncthreads();

    if (tid == 0) {
        float inp = input[b];
        float lg[SS], mx = -1e30f;
#pragma unroll
        for (int s = 0; s < SS; s++) {
            float v = battn[s] + Wattn[s * 1025] * inp
                    + s_part[0][s] + s_part[1][s] + s_part[2][s] + s_part[3][s];
            lg[s] = v; mx = fmaxf(mx, v);
        }
        float sum = 0.f;
#pragma unroll
        for (int s = 0; s < SS; s++) { lg[s] = __expf(lg[s] - mx); sum += lg[s]; }
        float inv = __fdividef(1.f, sum);
#pragma unroll
        for (int s = 0; s < SS; s++) {
            float w = lg[s] * inv;
            s_w[s] = w;
            out_attnw[(size_t)b * SS + s] = w;
        }
    }
    __syncthreads();

    float w0 = s_w[0], w1 = s_w[1], w2 = s_w[2], w3 = s_w[3], w4 = s_w[4], w5 = s_w[5];
    const float* eb = enc + (size_t)b * SS * HH;
    float4 e0 = *(const float4*)&eb[k4];
    float4 e1 = *(const float4*)&eb[HH + k4];
    float4 e2 = *(const float4*)&eb[2 * HH + k4];
    float4 e3 = *(const float4*)&eb[3 * HH + k4];
    float4 e4 = *(const float4*)&eb[4 * HH + k4];
    float4 e5 = *(const float4*)&eb[5 * HH + k4];
    float4 a;
    a.x = w0*e0.x + w1*e1.x + w2*e2.x + w3*e3.x + w4*e4.x + w5*e5.x;
    a.y = w0*e0.y + w1*e1.y + w2*e2.y + w3*e3.y + w4*e4.y + w5*e5.y;
    a.z = w0*e0.z + w1*e1.z + w2*e2.z + w3*e3.z + w4*e4.z + w5*e5.z;
    a.w = w0*e0.w + w1*e1.w + w2*e2.w + w3*e3.w + w4*e4.w + w5*e5.w;

    __half2* xc2 = (__half2*)&g_Xc[(size_t)b * KC];
    xc2[tid * 2]     = __floats2half2_rn(a.x, a.y);
    xc2[tid * 2 + 1] = __floats2half2_rn(a.z, a.w);
    __half2* ab2 = (__half2*)&g_Abig[(size_t)b * KG + 512];
    ab2[tid * 2]     = __floats2half2_rn(h4.x, h4.y);
    ab2[tid * 2 + 1] = __floats2half2_rn(h4.z, h4.w);

    if (tid < 64) {
        float v = 0.f;
        if (tid == 0) v = input[b];
        else if (tid == 1) v = 1.f;
        g_Xc[(size_t)b * KC + 512 + tid] = __float2half_rn(v);
        float u = (tid == 0) ? 1.f : 0.f;
        g_Abig[(size_t)b * KG + 1024 + tid] = __float2half_rn(u);
    }
}

// ---- fp16 wmma GEMM, 128x128 tile, 4 warps (64x64/warp), BK=64, 2-stage cp.async ----
// EPI 0: relu -> half C  (comb; C half, ldc halves)
// EPI 1: fused LSTM      (gates; interleaved N = 4*j+g; writes o_h/o_c f32)
#define CP16(dst_u32, src_ptr) \
    asm volatile("cp.async.cg.shared.global [%0], [%1], 16;" :: "r"(dst_u32), "l"(src_ptr))

template <int EPI>
__global__ void __launch_bounds__(128, 3)
gemm_fp16(const __half* __restrict__ A, int lda,
          const __half* __restrict__ Bw, int ldb,
          void* __restrict__ Cv, int ldc, int K,
          const float* __restrict__ cell,
          float* __restrict__ o_h, float* __restrict__ o_c) {
    constexpr int BM = 128, BN = 128, BK = 64, PAD = 72;   // PAD halves (144B rows)
    extern __shared__ __half smem[];
    __half* As = smem;                      // 2 stages * BM*PAD
    __half* Bs = smem + 2 * BM * PAD;       // 2 stages * BN*PAD

    int m0 = blockIdx.y * BM, n0 = blockIdx.x * BN;
    int tid = threadIdx.x;                  // 128 threads = 4 warps
    int warp = tid >> 5, lane = tid & 31;
    int wr = warp & 1;    // 64-row slab
    int wc = warp >> 1;   // 64-col slab

    wmma::fragment<wmma::accumulator, 16, 16, 16, float> acc[4][4];
#pragma unroll
    for (int i = 0; i < 4; i++)
#pragma unroll
        for (int j = 0; j < 4; j++) wmma::fill_fragment(acc[i][j], 0.f);

    int nk = K / BK;

    auto stage_copy = [&](int st, int k0) {
#pragma unroll
        for (int i = 0; i < 8; i++) {
            int q = tid + i * 128;
            int row = q >> 3, c8 = (q & 7) << 3;
            const __half* ga = &A[(size_t)(m0 + row) * lda + k0 + c8];
            unsigned int sa = (unsigned int)__cvta_generic_to_shared(&As[st * BM * PAD + row * PAD + c8]);
            CP16(sa, ga);
            const __half* gb = &Bw[(size_t)(n0 + row) * ldb + k0 + c8];
            unsigned int sb = (unsigned int)__cvta_generic_to_shared(&Bs[st * BN * PAD + row * PAD + c8]);
            CP16(sb, gb);
        }
        asm volatile("cp.async.commit_group;");
    };

    stage_copy(0, 0);

    for (int t = 0; t < nk; t++) {
        asm volatile("cp.async.wait_group 0;");
        __syncthreads();   // stage t visible; stage t-1 consumed -> buffer free
        if (t + 1 < nk) stage_copy((t + 1) & 1, (t + 1) * BK);

        const __half* Ab = &As[(t & 1) * BM * PAD];
        const __half* Bb = &Bs[(t & 1) * BN * PAD];

#pragma unroll
        for (int kk = 0; kk < 4; kk++) {     // 4 x k=16
            wmma::fragment<wmma::matrix_a, 16, 16, 16, __half, wmma::row_major> af[4];
            wmma::fragment<wmma::matrix_b, 16, 16, 16, __half, wmma::col_major> bf[4];
#pragma unroll
            for (int i = 0; i < 4; i++)
                wmma::load_matrix_sync(af[i], &Ab[(wr * 64 + i * 16) * PAD + kk * 16], PAD);
#pragma unroll
            for (int j = 0; j < 4; j++)
                wmma::load_matrix_sync(bf[j], &Bb[(wc * 64 + j * 16) * PAD + kk * 16], PAD);
#pragma unroll
            for (int i = 0; i < 4; i++)
#pragma unroll
                for (int j = 0; j < 4; j++)
                    wmma::mma_sync(acc[i][j], af[i], bf[j], acc[i][j]);
        }
    }

    // ---- epilogue: stage accumulators through smem ----
    __syncthreads();                      // mainloop smem dead, reuse as f32 staging
    float* stg = (float*)smem;
    constexpr int LDS_ = 68;
    float* wbase = stg + warp * 64 * LDS_;
#pragma unroll
    for (int i = 0; i < 4; i++)
#pragma unroll
        for (int j = 0; j < 4; j++)
            wmma::store_matrix_sync(&wbase[(i * 16) * LDS_ + j * 16], acc[i][j],
                                    LDS_, wmma::mem_row_major);
    __syncwarp();

    if (EPI == 0) {
        __half* Ch = (__half*)Cv;
        for (int r = lane; r < 64; r += 32) {
            size_t grow = (size_t)(m0 + wr * 64 + r) * ldc + n0 + wc * 64;
#pragma unroll
            for (int c = 0; c < 64; c += 2) {
                float x = fmaxf(wbase[r * LDS_ + c], 0.f);
                float y = fmaxf(wbase[r * LDS_ + c + 1], 0.f);
                *(__half2*)&Ch[grow + c] = __floats2half2_rn(x, y);
            }
        }
    } else {
        // fused LSTM: this warp's cols = interleaved gates for 16 hidden units
        int jbase = (n0 + wc * 64) >> 2;
#pragma unroll 4
        for (int it = 0; it < 32; it++) {
            int idx = it * 32 + lane;         // 0..1023 over (row, jj)
            int r = idx >> 4, jj = idx & 15;
            int b = m0 + wr * 64 + r;
            int j = jbase + jj;
            const float* cellrow = &wbase[r * LDS_ + jj * 4];
            float gi = cellrow[0], gf = cellrow[1], gg = cellrow[2], go = cellrow[3];
            float c_old = cell[(size_t)b * HH + j];
            float si = sigm_fast(gi);
            float sf = sigm_fast(gf);
            float so = sigm_fast(go);
            float tg = tanh_fast(gg);
            float cn = sf * c_old + si * tg;
            float hn = so * tanh_fast(cn);
            o_c[(size_t)b * HH + j] = cn;
            o_h[(size_t)b * HH + j] = hn;
        }
    }
}

// ---- output dot: out[b] = dot(o_h[b,:], Wout) + bout ----
__global__ void dot_kernel(const float* __restrict__ o_h, const float* __restrict__ Wout,
                           const float* __restrict__ bout, float* __restrict__ out_output) {
    int b = blockIdx.x, j = threadIdx.x;   // 512 threads
    float part = o_h[(size_t)b * HH + j] * Wout[j];
#pragma unroll
    for (int off = 16; off; off >>= 1) part += __shfl_down_sync(0xffffffffu, part, off);
    __shared__ float sp[16];
    if ((j & 31) == 0) sp[j >> 5] = part;
    __syncthreads();
    if (j < 16) {
        float v = sp[j];
#pragma unroll
        for (int off = 8; off; off >>= 1) v += __shfl_down_sync(0xffffu, v, off);
        if (j == 0) out_output[b] = v + bout[0];
    }
}

extern "C" void kernel_launch(void* const* d_in, const int* in_sizes, int n_in,
                              void* d_out, int out_size) {
    const float* input  = (const float*)d_in[0];
    const float* hidden = (const float*)d_in[1];
    const float* cell   = (const float*)d_in[2];
    const float* enc    = (const float*)d_in[3];
    const float* Wattn  = (const float*)d_in[4];
    const float* battn  = (const float*)d_in[5];
    const float* Wcomb  = (const float*)d_in[6];
    const float* bcomb  = (const float*)d_in[7];
    const float* Wih    = (const float*)d_in[8];
    const float* Whh    = (const float*)d_in[9];
    const float* bih    = (const float*)d_in[10];
    const float* bhh    = (const float*)d_in[11];
    const float* Wout   = (const float*)d_in[12];
    const float* bout   = (const float*)d_in[13];

    int B = in_sizes[1] / HH;   // 16384

    float* out      = (float*)d_out;
    float* o_output = out;                              // [B, 1]
    float* o_h      = out + (size_t)B;                  // [B, H]
    float* o_c      = o_h + (size_t)B * HH;             // [B, H]
    float* o_aw     = o_c + (size_t)B * HH;             // [B, 1, S]

    __half *pXc, *pAbig, *pWc, *pWg;
    cudaGetSymbolAddress((void**)&pXc,    g_Xc);
    cudaGetSymbolAddress((void**)&pAbig,  g_Abig);
    cudaGetSymbolAddress((void**)&pWc,    g_Wc);
    cudaGetSymbolAddress((void**)&pWg,    g_Wg);

    constexpr int SMEMB = 2 * 2 * 128 * 72 * (int)sizeof(__half);   // 73728
    cudaFuncSetAttribute((const void*)gemm_fp16<0>,
                         cudaFuncAttributeMaxDynamicSharedMemorySize, SMEMB);
    cudaFuncSetAttribute((const void*)gemm_fp16<1>,
                         cudaFuncAttributeMaxDynamicSharedMemorySize, SMEMB);

    init_weights<<<512, 256>>>(Wcomb, bcomb, Wih, Whh, bih, bhh);
    attn_kernel<<<B, 128>>>(input, hidden, cell, enc, Wattn, battn, o_aw);

    // comb: Abig[:, 0:512] = relu(Xc @ Wc^T)  -> half into g_Abig
    {
        dim3 grid(HH / 128, B / 128);
        gemm_fp16<0><<<grid, 128, SMEMB>>>(pXc, KC, pWc, KC, pAbig, KG, KC,
                                           nullptr, nullptr, nullptr);
    }
    // gates GEMM with fused LSTM epilogue -> o_h, o_c
    {
        dim3 grid((4 * HH) / 128, B / 128);
        gemm_fp16<1><<<grid, 128, SMEMB>>>(pAbig, KG, pWg, KG, nullptr, 0, KG,
                                           cell, o_h, o_c);
    }
    dot_kernel<<<B, 512>>>(o_h, Wout, bout, o_output);
}

// round 14
// speedup vs baseline: 1.2972x; 1.0918x over previous
#include <cuda_runtime.h>
#include <cstdint>
#include <cuda_fp16.h>
#include <mma.h>
#include <math.h>

using namespace nvcuda;

#define HH 512
#define SS 6
#define MAXB 16384
#define KC 576      // comb K: 512 attn_applied + input + bias + pad to 64
#define KG 1088     // gates K: 512 x + 512 hidden + bias + pad to 64

// ---- scratch (static device globals; no runtime allocation) ----
__device__ __align__(16) __half g_Xc  [(size_t)MAXB * KC];
__device__ __align__(16) __half g_Abig[(size_t)MAXB * KG];
__device__ __align__(16) __half g_Wc  [HH * KC];
__device__ __align__(16) __half g_Wg  [4 * HH * KG];   // rows interleaved: n' = 4*j + gate

__device__ __forceinline__ float sigm_fast(float x) {
    return __fdividef(1.f, 1.f + __expf(-x));
}
__device__ __forceinline__ float tanh_fast(float x) {
    return __fmaf_rn(2.f, sigm_fast(2.f * x), -1.f);
}

// ---- build padded weight matrices (fp16) ----
// g_Wg row n' = 4*j + g  maps to torch row  n_old = g*512 + j  (gate order i,f,g,o)
__global__ void init_weights(const float* __restrict__ Wcomb, const float* __restrict__ bcomb,
                             const float* __restrict__ Wih,   const float* __restrict__ Whh,
                             const float* __restrict__ bih,   const float* __restrict__ bhh) {
    int idx = blockIdx.x * blockDim.x + threadIdx.x;
    int stride = gridDim.x * blockDim.x;
    for (int i = idx; i < HH * KC; i += stride) {
        int n = i / KC, k = i % KC;
        float v = 0.f;
        if (k < 512)        v = Wcomb[n * 513 + 1 + k];
        else if (k == 512)  v = Wcomb[n * 513];
        else if (k == 513)  v = bcomb[n];
        g_Wc[i] = __float2half_rn(v);
    }
    for (int i = idx; i < 4 * HH * KG; i += stride) {
        int np = i / KG, k = i % KG;
        int j = np >> 2, g = np & 3;
        int n = g * 512 + j;               // torch gate-major row
        float v = 0.f;
        if (k < 512)        v = Wih[n * 512 + k];
        else if (k < 1024)  v = Whh[n * 512 + (k - 512)];
        else if (k == 1024) v = bih[n] + bhh[n];
        g_Wg[i] = __float2half_rn(v);
    }
}

// ---- attention (R11 version: 256 threads, best measured) ----
__global__ void attn_kernel(const float* __restrict__ input, const float* __restrict__ hidden,
                            const float* __restrict__ cell,  const float* __restrict__ enc,
                            const float* __restrict__ Wattn, const float* __restrict__ battn,
                            float* __restrict__ out_attnw) {
    int b = blockIdx.x;
    int tid = threadIdx.x;             // 256 threads
    __shared__ float s_w[SS];
    __shared__ float s_part[8][SS];

    float h0 = hidden[(size_t)b * HH + tid];
    float h1 = hidden[(size_t)b * HH + tid + 256];
    float c0 = cell  [(size_t)b * HH + tid];
    float c1 = cell  [(size_t)b * HH + tid + 256];

    float p[SS];
#pragma unroll
    for (int s = 0; s < SS; s++) {
        const float* wr = Wattn + s * 1025;
        p[s] = wr[1 + tid] * h0 + wr[1 + tid + 256] * h1
             + wr[513 + tid] * c0 + wr[513 + tid + 256] * c1;
    }
#pragma unroll
    for (int s = 0; s < SS; s++)
#pragma unroll
        for (int off = 16; off; off >>= 1)
            p[s] += __shfl_down_sync(0xffffffffu, p[s], off);
    int warp = tid >> 5, lane = tid & 31;
    if (lane == 0)
#pragma unroll
        for (int s = 0; s < SS; s++) s_part[warp][s] = p[s];
    __syncthreads();

    if (tid == 0) {
        float inp = input[b];
        float lg[SS], mx = -1e30f;
#pragma unroll
        for (int s = 0; s < SS; s++) {
            float v = battn[s] + Wattn[s * 1025] * inp;
#pragma unroll
            for (int w = 0; w < 8; w++) v += s_part[w][s];
            lg[s] = v; mx = fmaxf(mx, v);
        }
        float sum = 0.f;
#pragma unroll
        for (int s = 0; s < SS; s++) { lg[s] = __expf(lg[s] - mx); sum += lg[s]; }
        float inv = __fdividef(1.f, sum);
#pragma unroll
        for (int s = 0; s < SS; s++) {
            float w = lg[s] * inv;
            s_w[s] = w;
            out_attnw[(size_t)b * SS + s] = w;
        }
    }
    __syncthreads();

    float w0 = s_w[0], w1 = s_w[1], w2 = s_w[2], w3 = s_w[3], w4 = s_w[4], w5 = s_w[5];
    const float* eb = enc + (size_t)b * SS * HH;
#pragma unroll
    for (int r = 0; r < 2; r++) {
        int k = tid + r * 256;
        float a = w0 * eb[k]          + w1 * eb[HH + k]     + w2 * eb[2 * HH + k]
                + w3 * eb[3 * HH + k] + w4 * eb[4 * HH + k] + w5 * eb[5 * HH + k];
        g_Xc[(size_t)b * KC + k] = __float2half_rn(a);
        g_Abig[(size_t)b * KG + 512 + k] = __float2half_rn((r == 0) ? h0 : h1);
    }
    if (tid < 64) {
        float v = 0.f;
        if (tid == 0) v = input[b];
        else if (tid == 1) v = 1.f;
        g_Xc[(size_t)b * KC + 512 + tid] = __float2half_rn(v);
        float u = (tid == 0) ? 1.f : 0.f;
        g_Abig[(size_t)b * KG + 1024 + tid] = __float2half_rn(u);
    }
}

// ---- fp16 wmma GEMM, 64x128 CTA tile, 4 warps (32x64/warp), BK=64,
//      2-stage cp.async, 4 CTAs/SM (16 warps/SM) ----
// EPI 0: relu -> half C  (comb; C half, ldc halves)
// EPI 1: fused LSTM      (gates; interleaved N = 4*j+g; writes o_h/o_c f32)
#define CP16(dst_u32, src_ptr) \
    asm volatile("cp.async.cg.shared.global [%0], [%1], 16;" :: "r"(dst_u32), "l"(src_ptr))

template <int EPI>
__global__ void __launch_bounds__(128, 4)
gemm_fp16(const __half* __restrict__ A, int lda,
          const __half* __restrict__ Bw, int ldb,
          void* __restrict__ Cv, int ldc, int K,
          const float* __restrict__ cell,
          float* __restrict__ o_h, float* __restrict__ o_c) {
    constexpr int BM = 64, BN = 128, BK = 64, PAD = 72;   // PAD halves (144B rows)
    extern __shared__ __half smem[];
    __half* As = smem;                      // 2 stages * BM*PAD
    __half* Bs = smem + 2 * BM * PAD;       // 2 stages * BN*PAD

    int m0 = blockIdx.y * BM, n0 = blockIdx.x * BN;
    int tid = threadIdx.x;                  // 128 threads = 4 warps
    int warp = tid >> 5, lane = tid & 31;
    int wr = warp & 1;    // 0..1 -> 32-row slab
    int wc = warp >> 1;   // 0..1 -> 64-col slab

    wmma::fragment<wmma::accumulator, 16, 16, 16, float> acc[2][4];
#pragma unroll
    for (int i = 0; i < 2; i++)
#pragma unroll
        for (int j = 0; j < 4; j++) wmma::fill_fragment(acc[i][j], 0.f);

    int nk = K / BK;

    auto stage_copy = [&](int st, int k0) {
#pragma unroll
        for (int i = 0; i < 4; i++) {       // A: 64 rows x 8 chunks = 512
            int q = tid + i * 128;
            int row = q >> 3, c8 = (q & 7) << 3;
            const __half* ga = &A[(size_t)(m0 + row) * lda + k0 + c8];
            unsigned int sa = (unsigned int)__cvta_generic_to_shared(&As[st * BM * PAD + row * PAD + c8]);
            CP16(sa, ga);
        }
#pragma unroll
        for (int i = 0; i < 8; i++) {       // B: 128 rows x 8 chunks = 1024
            int q = tid + i * 128;
            int row = q >> 3, c8 = (q & 7) << 3;
            const __half* gb = &Bw[(size_t)(n0 + row) * ldb + k0 + c8];
            unsigned int sb = (unsigned int)__cvta_generic_to_shared(&Bs[st * BN * PAD + row * PAD + c8]);
            CP16(sb, gb);
        }
        asm volatile("cp.async.commit_group;");
    };

    stage_copy(0, 0);

    for (int t = 0; t < nk; t++) {
        asm volatile("cp.async.wait_group 0;");
        __syncthreads();   // stage t visible; stage t-1 consumed -> buffer free
        if (t + 1 < nk) stage_copy((t + 1) & 1, (t + 1) * BK);

        const __half* Ab = &As[(t & 1) * BM * PAD];
        const __half* Bb = &Bs[(t & 1) * BN * PAD];

#pragma unroll
        for (int kk = 0; kk < 4; kk++) {     // 4 x k=16
            wmma::fragment<wmma::matrix_a, 16, 16, 16, __half, wmma::row_major> af[2];
            wmma::fragment<wmma::matrix_b, 16, 16, 16, __half, wmma::col_major> bf[4];
#pragma unroll
            for (int i = 0; i < 2; i++)
                wmma::load_matrix_sync(af[i], &Ab[(wr * 32 + i * 16) * PAD + kk * 16], PAD);
#pragma unroll
            for (int j = 0; j < 4; j++)
                wmma::load_matrix_sync(bf[j], &Bb[(wc * 64 + j * 16) * PAD + kk * 16], PAD);
#pragma unroll
            for (int i = 0; i < 2; i++)
#pragma unroll
                for (int j = 0; j < 4; j++)
                    wmma::mma_sync(acc[i][j], af[i], bf[j], acc[i][j]);
        }
    }

    // ---- epilogue: stage accumulators through smem ----
    __syncthreads();                      // mainloop smem dead, reuse as f32 staging
    float* stg = (float*)smem;
    constexpr int LDS_ = 68;
    float* wbase = stg + warp * 32 * LDS_;   // 32 rows x 68 f32 per warp (fits 55KB)
#pragma unroll
    for (int i = 0; i < 2; i++)
#pragma unroll
        for (int j = 0; j < 4; j++)
            wmma::store_matrix_sync(&wbase[(i * 16) * LDS_ + j * 16], acc[i][j],
                                    LDS_, wmma::mem_row_major);
    __syncwarp();

    if (EPI == 0) {
        __half* Ch = (__half*)Cv;
        {
            int r = lane;                 // 32 lanes cover the 32 rows
            size_t grow = (size_t)(m0 + wr * 32 + r) * ldc + n0 + wc * 64;
#pragma unroll
            for (int c = 0; c < 64; c += 2) {
                float x = fmaxf(wbase[r * LDS_ + c], 0.f);
                float y = fmaxf(wbase[r * LDS_ + c + 1], 0.f);
                *(__half2*)&Ch[grow + c] = __floats2half2_rn(x, y);
            }
        }
    } else {
        // fused LSTM: this warp's 64 cols = interleaved gates for 16 hidden units
        int nbase = n0 + wc * 64;
        int jbase = nbase >> 2;
#pragma unroll 4
        for (int it = 0; it < 16; it++) {
            int idx = it * 32 + lane;         // 0..511 over (row, jj)
            int r = idx >> 4, jj = idx & 15;
            int b = m0 + wr * 32 + r;
            int j = jbase + jj;
            const float* cellrow = &wbase[r * LDS_ + jj * 4];
            float gi = cellrow[0], gf = cellrow[1], gg = cellrow[2], go = cellrow[3];
            float c_old = cell[(size_t)b * HH + j];
            float si = sigm_fast(gi);
            float sf = sigm_fast(gf);
            float so = sigm_fast(go);
            float tg = tanh_fast(gg);
            float cn = sf * c_old + si * tg;
            float hn = so * tanh_fast(cn);
            o_c[(size_t)b * HH + j] = cn;
            o_h[(size_t)b * HH + j] = hn;
        }
    }
}

// ---- output dot: out[b] = dot(o_h[b,:], Wout) + bout ----
__global__ void dot_kernel(const float* __restrict__ o_h, const float* __restrict__ Wout,
                           const float* __restrict__ bout, float* __restrict__ out_output) {
    int b = blockIdx.x, j = threadIdx.x;   // 512 threads
    float part = o_h[(size_t)b * HH + j] * Wout[j];
#pragma unroll
    for (int off = 16; off; off >>= 1) part += __shfl_down_sync(0xffffffffu, part, off);
    __shared__ float sp[16];
    if ((j & 31) == 0) sp[j >> 5] = part;
    __syncthreads();
    if (j < 16) {
        float v = sp[j];
#pragma unroll
        for (int off = 8; off; off >>= 1) v += __shfl_down_sync(0xffffu, v, off);
        if (j == 0) out_output[b] = v + bout[0];
    }
}

extern "C" void kernel_launch(void* const* d_in, const int* in_sizes, int n_in,
                              void* d_out, int out_size) {
    const float* input  = (const float*)d_in[0];
    const float* hidden = (const float*)d_in[1];
    const float* cell   = (const float*)d_in[2];
    const float* enc    = (const float*)d_in[3];
    const float* Wattn  = (const float*)d_in[4];
    const float* battn  = (const float*)d_in[5];
    const float* Wcomb  = (const float*)d_in[6];
    const float* bcomb  = (const float*)d_in[7];
    const float* Wih    = (const float*)d_in[8];
    const float* Whh    = (const float*)d_in[9];
    const float* bih    = (const float*)d_in[10];
    const float* bhh    = (const float*)d_in[11];
    const float* Wout   = (const float*)d_in[12];
    const float* bout   = (const float*)d_in[13];

    int B = in_sizes[1] / HH;   // 16384

    float* out      = (float*)d_out;
    float* o_output = out;                              // [B, 1]
    float* o_h      = out + (size_t)B;                  // [B, H]
    float* o_c      = o_h + (size_t)B * HH;             // [B, H]
    float* o_aw     = o_c + (size_t)B * HH;             // [B, 1, S]

    __half *pXc, *pAbig, *pWc, *pWg;
    cudaGetSymbolAddress((void**)&pXc,    g_Xc);
    cudaGetSymbolAddress((void**)&pAbig,  g_Abig);
    cudaGetSymbolAddress((void**)&pWc,    g_Wc);
    cudaGetSymbolAddress((void**)&pWg,    g_Wg);

    // smem: 2 stages * (64 + 128) rows * 72 halves * 2B = 55296
    constexpr int SMEMB = 2 * (64 + 128) * 72 * (int)sizeof(__half);
    cudaFuncSetAttribute((const void*)gemm_fp16<0>,
                         cudaFuncAttributeMaxDynamicSharedMemorySize, SMEMB);
    cudaFuncSetAttribute((const void*)gemm_fp16<1>,
                         cudaFuncAttributeMaxDynamicSharedMemorySize, SMEMB);

    init_weights<<<512, 256>>>(Wcomb, bcomb, Wih, Whh, bih, bhh);
    attn_kernel<<<B, 256>>>(input, hidden, cell, enc, Wattn, battn, o_aw);

    // comb: Abig[:, 0:512] = relu(Xc @ Wc^T)  -> half into g_Abig
    {
        dim3 grid(HH / 128, B / 64);
        gemm_fp16<0><<<grid, 128, SMEMB>>>(pXc, KC, pWc, KC, pAbig, KG, KC,
                                           nullptr, nullptr, nullptr);
    }
    // gates GEMM with fused LSTM epilogue -> o_h, o_c
    {
        dim3 grid((4 * HH) / 128, B / 64);
        gemm_fp16<1><<<grid, 128, SMEMB>>>(pAbig, KG, pWg, KG, nullptr, 0, KG,
                                           cell, o_h, o_c);
    }
    dot_kernel<<<B, 512>>>(o_h, Wout, bout, o_output);
}